// round 11
// baseline (speedup 1.0000x reference)
#include <cuda_runtime.h>
#include <cuda_fp16.h>
#include <stdint.h>

#define NN 100000
#define EMAX 1200000
#define C 64
#define NB 444   // 3 blocks/SM * 148 SMs -> all co-resident (barrier-safe)

// ---------------- scratch (device globals; no allocation allowed) ----------
__device__ __half g_ha[NN * C];
__device__ __half g_hb[NN * C];
__device__ __half g_w1h[C * C];
__device__ __half g_w2h[C * C];
__device__ float  g_dinv[NN];
__device__ int    g_deg[NN];
__device__ int    g_rowptr[NN];
__device__ int    g_cursor[NN];
__device__ int    g_col[EMAX];
__device__ int    g_total;
__device__ int    g_is64;
__device__ int    g_barA[8];
__device__ int    g_barD[8];

// ---------------- device-wide barrier (self-resetting, replay-safe) ---------
__device__ __forceinline__ void grid_barrier(int slot) {
    __syncthreads();
    __threadfence();                     // every thread publishes its writes
    if (threadIdx.x == 0) {
        atomicAdd(&g_barA[slot], 1);
        while (atomicAdd(&g_barA[slot], 0) < NB) __nanosleep(64);
        __threadfence();
        int d = atomicAdd(&g_barD[slot], 1);
        if (d == NB - 1) {
            atomicExch(&g_barA[slot], 0);
            atomicExch(&g_barD[slot], 0);
        }
    }
    __syncthreads();
}

__device__ __forceinline__ int blk_excl_scan256(int v, int* tot) {
    __shared__ int ws[8];
    int lane = threadIdx.x & 31, w = threadIdx.x >> 5;
    int x = v;
#pragma unroll
    for (int o = 1; o < 32; o <<= 1) {
        int u = __shfl_up_sync(0xffffffffu, x, o);
        if (lane >= o) x += u;
    }
    if (lane == 31) ws[w] = x;
    __syncthreads();
    if (w == 0) {
        int s = (lane < 8) ? ws[lane] : 0;
#pragma unroll
        for (int o = 1; o < 8; o <<= 1) {
            int u = __shfl_up_sync(0xffffffffu, s, o);
            if (lane >= o) s += u;
        }
        if (lane < 8) ws[lane] = s;
    }
    __syncthreads();
    *tot = ws[7];
    int excl = x - v + (w ? ws[w - 1] : 0);
    __syncthreads();
    return excl;
}

// index load: when data is int64 read only the low 32-bit word
__device__ __forceinline__ int load_idx(const void* eiv, long long pos) {
    if (g_is64) return ((const int*)eiv)[pos << 1];
    return ((const int*)eiv)[pos];
}

// ---------------- tensor-core GEMM pieces ------------------------------------
#define AS_STR 72
#define AS_BYTES (128 * AS_STR * 2)      // 18432
#define WS_BYTES (64 * AS_STR * 2)       // 9216

__device__ __forceinline__ void ldsm4(uint32_t& r0, uint32_t& r1,
                                      uint32_t& r2, uint32_t& r3, uint32_t a) {
    asm volatile("ldmatrix.sync.aligned.m8n8.x4.shared.b16 {%0,%1,%2,%3}, [%4];"
                 : "=r"(r0), "=r"(r1), "=r"(r2), "=r"(r3) : "r"(a));
}
__device__ __forceinline__ void ldsm4t(uint32_t& r0, uint32_t& r1,
                                       uint32_t& r2, uint32_t& r3, uint32_t a) {
    asm volatile("ldmatrix.sync.aligned.m8n8.x4.trans.shared.b16 {%0,%1,%2,%3}, [%4];"
                 : "=r"(r0), "=r"(r1), "=r"(r2), "=r"(r3) : "r"(a));
}
__device__ __forceinline__ void mma16816(float* d, uint32_t a0, uint32_t a1,
                                         uint32_t a2, uint32_t a3,
                                         uint32_t b0, uint32_t b1) {
    asm volatile(
        "mma.sync.aligned.m16n8k16.row.col.f32.f16.f16.f32 "
        "{%0,%1,%2,%3}, {%4,%5,%6,%7}, {%8,%9}, {%0,%1,%2,%3};"
        : "+f"(d[0]), "+f"(d[1]), "+f"(d[2]), "+f"(d[3])
        : "r"(a0), "r"(a1), "r"(a2), "r"(a3), "r"(b0), "r"(b1));
}

__device__ __forceinline__ void load_a_tile(const float* __restrict__ X,
                                            __half* As, int row0, int N, int tid) {
    const float4* X4 = (const float4*)(X + (size_t)row0 * C);
#pragma unroll
    for (int i = 0; i < 8; i++) {
        int j = tid + 256 * i;
        int r = j >> 4, c = (j & 15) * 4;
        float4 v = make_float4(0.f, 0.f, 0.f, 0.f);
        if (row0 + r < N) v = X4[j];
        *(__half2*)&As[r * AS_STR + c]     = __floats2half2_rn(v.x, v.y);
        *(__half2*)&As[r * AS_STR + c + 2] = __floats2half2_rn(v.z, v.w);
    }
}
__device__ __forceinline__ void load_a_tile(const __half* __restrict__ X,
                                            __half* As, int row0, int N, int tid) {
    const uint4* X8 = (const uint4*)(X + (size_t)row0 * C);
#pragma unroll
    for (int i = 0; i < 4; i++) {
        int j = tid + 256 * i;
        int r = j >> 3, c = (j & 7) * 8;
        uint4 v = make_uint4(0, 0, 0, 0);
        if (row0 + r < N) v = __ldcg(&X8[j]);
        *(uint4*)&As[r * AS_STR + c] = v;
    }
}

template <typename T>
__device__ __forceinline__ void gemm_body(const T* __restrict__ X,
                                          const __half* __restrict__ Wh,
                                          __half* __restrict__ H, int N,
                                          int bid, __half* As, __half* Wsm) {
    int tid  = threadIdx.x;
    int row0 = bid * 128;

    {
        const uint4* W8 = (const uint4*)Wh;
#pragma unroll
        for (int i = 0; i < 2; i++) {
            int j = tid + 256 * i;
            int r = j >> 3, c = (j & 7) * 8;
            *(uint4*)&Wsm[r * AS_STR + c] = W8[j];
        }
    }
    load_a_tile(X, As, row0, N, tid);
    __syncthreads();

    int w    = tid >> 5;
    int lane = tid & 31;
    int R    = w * 16;
    int l8   = lane & 7;
    int mb0  = (lane >> 3) & 1;
    int mb1  = (lane >> 4) & 1;

    float d[8][4];
#pragma unroll
    for (int i = 0; i < 8; i++)
#pragma unroll
        for (int j = 0; j < 4; j++) d[i][j] = 0.f;

    uint32_t a_base = (uint32_t)__cvta_generic_to_shared(As);
    uint32_t w_base = (uint32_t)__cvta_generic_to_shared(Wsm);

#pragma unroll
    for (int kk = 0; kk < 4; kk++) {
        uint32_t a0, a1, a2, a3;
        uint32_t aaddr = a_base +
            ((R + mb0 * 8 + l8) * AS_STR + kk * 16 + mb1 * 8) * 2;
        ldsm4(a0, a1, a2, a3, aaddr);
#pragma unroll
        for (int np = 0; np < 4; np++) {
            uint32_t b0, b1, b2, b3;
            uint32_t baddr = w_base +
                ((kk * 16 + mb0 * 8 + l8) * AS_STR + np * 16 + mb1 * 8) * 2;
            ldsm4t(b0, b1, b2, b3, baddr);
            mma16816(d[np * 2],     a0, a1, a2, a3, b0, b1);
            mma16816(d[np * 2 + 1], a0, a1, a2, a3, b2, b3);
        }
    }

    int g4 = lane >> 2, t4 = lane & 3;
    int r0g = row0 + R + g4;
    int r1g = r0g + 8;
    float dn0 = (r0g < N) ? g_dinv[r0g] : 0.f;
    float dn1 = (r1g < N) ? g_dinv[r1g] : 0.f;
#pragma unroll
    for (int nt = 0; nt < 8; nt++) {
        int coff = nt * 8 + t4 * 2;
        if (r0g < N)
            *(__half2*)(H + (size_t)r0g * C + coff) =
                __floats2half2_rn(d[nt][0] * dn0, d[nt][1] * dn0);
        if (r1g < N)
            *(__half2*)(H + (size_t)r1g * C + coff) =
                __floats2half2_rn(d[nt][2] * dn1, d[nt][3] * dn1);
    }
    __syncthreads();   // smem reused by next virtual tile
}

// ---------------- aggregation body: 4 nodes per warp -------------------------
// __ldcg on H: L1 may hold stale g_ha lines cached by the earlier agg phase.
template <bool HALF_OUT, bool RELU>
__device__ __forceinline__ void agg_body(const __half* __restrict__ H,
                                         const float* __restrict__ bias,
                                         void* __restrict__ outv, int N,
                                         int bid) {
    const unsigned F = 0xffffffffu;
    int lt   = bid * 256 + threadIdx.x;
    int warp = lt >> 5;
    int lane = lt & 31;
    int g    = lane >> 3;
    int l8   = lane & 7;
    int n    = warp * 4 + g;
    bool act = (n < N);

    int beg = 0, len = 0;
    if (act) { beg = g_rowptr[n]; len = g_deg[n]; }
    int lm = len;
    lm = max(lm, __shfl_xor_sync(F, lm, 8));
    lm = max(lm, __shfl_xor_sync(F, lm, 16));

    float a0=0.f,a1=0.f,a2=0.f,a3=0.f,a4=0.f,a5=0.f,a6=0.f,a7=0.f;
    for (int off = 0; off < lm; off += 8) {
        int cnt = min(len - off, 8);
        int sp  = (l8 < cnt) ? g_col[beg + off + l8] : 0;
        int cm  = cnt;
        cm = max(cm, __shfl_xor_sync(F, cm, 8));
        cm = max(cm, __shfl_xor_sync(F, cm, 16));
#pragma unroll 4
        for (int j = 0; j < cm; j++) {
            int   s = __shfl_sync(F, sp, (g << 3) + j);
            float m = (j < cnt) ? 1.f : 0.f;
            uint4 v = __ldcg((const uint4*)(H + (size_t)s * C + l8 * 8));
            float2 f0 = __half22float2(*(__half2*)&v.x);
            float2 f1 = __half22float2(*(__half2*)&v.y);
            float2 f2 = __half22float2(*(__half2*)&v.z);
            float2 f3 = __half22float2(*(__half2*)&v.w);
            a0 += m * f0.x; a1 += m * f0.y; a2 += m * f1.x; a3 += m * f1.y;
            a4 += m * f2.x; a5 += m * f2.y; a6 += m * f3.x; a7 += m * f3.y;
        }
    }

    if (act) {
        float dn = g_dinv[n];
        uint4 hv = __ldcg((const uint4*)(H + (size_t)n * C + l8 * 8));
        float2 h0 = __half22float2(*(__half2*)&hv.x);
        float2 h1 = __half22float2(*(__half2*)&hv.y);
        float2 h2 = __half22float2(*(__half2*)&hv.z);
        float2 h3 = __half22float2(*(__half2*)&hv.w);
        float4 bA = *(const float4*)(bias + l8 * 8);
        float4 bB = *(const float4*)(bias + l8 * 8 + 4);
        float r0 = dn * (a0 + h0.x) + bA.x;
        float r1 = dn * (a1 + h0.y) + bA.y;
        float r2 = dn * (a2 + h1.x) + bA.z;
        float r3 = dn * (a3 + h1.y) + bA.w;
        float r4 = dn * (a4 + h2.x) + bB.x;
        float r5 = dn * (a5 + h2.y) + bB.y;
        float r6 = dn * (a6 + h3.x) + bB.z;
        float r7 = dn * (a7 + h3.y) + bB.w;
        if (RELU) {
            r0 = fmaxf(r0, 0.f); r1 = fmaxf(r1, 0.f);
            r2 = fmaxf(r2, 0.f); r3 = fmaxf(r3, 0.f);
            r4 = fmaxf(r4, 0.f); r5 = fmaxf(r5, 0.f);
            r6 = fmaxf(r6, 0.f); r7 = fmaxf(r7, 0.f);
        }
        if (HALF_OUT) {
            __half2 o0 = __floats2half2_rn(r0, r1);
            __half2 o1 = __floats2half2_rn(r2, r3);
            __half2 o2 = __floats2half2_rn(r4, r5);
            __half2 o3 = __floats2half2_rn(r6, r7);
            uint4 pk = make_uint4(*(uint32_t*)&o0, *(uint32_t*)&o1,
                                  *(uint32_t*)&o2, *(uint32_t*)&o3);
            *(uint4*)((__half*)outv + (size_t)n * C + l8 * 8) = pk;
        } else {
            float* o = (float*)outv + (size_t)n * C + l8 * 8;
            *(float4*)o       = make_float4(r0, r1, r2, r3);
            *(float4*)(o + 4) = make_float4(r4, r5, r6, r7);
        }
    }
}

// ---------------- the persistent mega-kernel ---------------------------------
__global__ void __launch_bounds__(256, 3) k_mega(
        const float* __restrict__ x, const void* __restrict__ eiv,
        const float* __restrict__ W1, const float* __restrict__ b1,
        const float* __restrict__ W2, const float* __restrict__ b2,
        float* __restrict__ out, int N, int E, int CH) {
    // ONE shared buffer for all gemm invocations (both template instantiations)
    __shared__ __align__(16) char smem_buf[AS_BYTES + WS_BYTES];
    __half* As  = (__half*)smem_buf;
    __half* Wsm = (__half*)(smem_buf + AS_BYTES);

    int b = blockIdx.x, t = threadIdx.x;

    // ---- P0: zero deg, reset counter, dtype probe, W1/W2 -> fp16 ----
    for (int i = b * 256 + t; i < N; i += NB * 256) g_deg[i] = 0;
    if (b == 0) {
        __shared__ int anz;
        if (t == 0) { anz = 0; g_total = 0; }
        __syncthreads();
        int e = t * (E / 256);
        if (((const int*)eiv)[2 * e + 1] != 0) anz = 1;
        __syncthreads();
        if (t == 0) g_is64 = (anz == 0);
    }
    if (b == 1 || b == 2) {
        const float* Wsrc = (b == 2) ? W2 : W1;
        __half* Wdst = (b == 2) ? g_w2h : g_w1h;
        const float4* W4 = (const float4*)Wsrc;
#pragma unroll
        for (int i = 0; i < 4; i++) {
            int j = t + 256 * i;
            float4 v = W4[j];
            __half2 h0 = __floats2half2_rn(v.x, v.y);
            __half2 h1 = __floats2half2_rn(v.z, v.w);
            *(uint2*)&Wdst[j * 4] = make_uint2(*(uint32_t*)&h0, *(uint32_t*)&h1);
        }
    }
    grid_barrier(0);

    // ---- P1: degree histogram ----
    for (int e = b * 256 + t; e < E; e += NB * 256) {
        int d = load_idx(eiv, (long long)E + e);
        if ((unsigned)d < (unsigned)NN) atomicAdd(&g_deg[d], 1);
    }
    grid_barrier(1);

    // ---- P2: per-block scan + atomic CSR base; dinv ----
    {
        __shared__ int base;
        int i = b * CH + t;
        bool ok = (t < CH && i < N);
        int v = ok ? g_deg[i] : 0;
        int tot;
        int ex = blk_excl_scan256(v, &tot);
        if (t == 0) base = atomicAdd(&g_total, tot);
        __syncthreads();
        if (ok) {
            int r = base + ex;
            g_rowptr[i] = r;
            g_cursor[i] = r;
            g_dinv[i]   = rsqrtf((float)(v + 1));
        }
    }
    grid_barrier(2);

    // ---- P3: CSR scatter + GEMM1 ----
    for (int e = b * 256 + t; e < E; e += NB * 256) {
        int s = load_idx(eiv, e);
        int d = load_idx(eiv, (long long)E + e);
        if ((unsigned)s < (unsigned)NN && (unsigned)d < (unsigned)NN) {
            int p = atomicAdd(&g_cursor[d], 1);
            g_col[p] = s;
        }
    }
    {
        int GB = (N + 127) / 128;
        for (int vb = b; vb < GB; vb += NB)
            gemm_body<float>(x, g_w1h, g_ha, N, vb, As, Wsm);
    }
    grid_barrier(3);

    // ---- P4: agg1 (relu, fp16 out) ----
    {
        int AGB = (N + 31) / 32;
        for (int vb = b; vb < AGB; vb += NB)
            agg_body<true, true>(g_ha, b1, g_hb, N, vb);
    }
    grid_barrier(4);

    // ---- P5: GEMM2 ----
    {
        int GB = (N + 127) / 128;
        for (int vb = b; vb < GB; vb += NB)
            gemm_body<__half>(g_hb, g_w2h, g_ha, N, vb, As, Wsm);
    }
    grid_barrier(5);

    // ---- P6: agg2 (fp32 out) ----
    {
        int AGB = (N + 31) / 32;
        for (int vb = b; vb < AGB; vb += NB)
            agg_body<false, false>(g_ha, b2, out, N, vb);
    }
}

// ---------------- launch ------------------------------------------------------
extern "C" void kernel_launch(void* const* d_in, const int* in_sizes, int n_in,
                              void* d_out, int out_size) {
    const float* x   = (const float*)d_in[0];
    const void*  ei  = d_in[1];
    const float* W1  = (const float*)d_in[2];
    const float* b1  = (const float*)d_in[3];
    const float* W2  = (const float*)d_in[4];
    const float* b2  = (const float*)d_in[5];
    float*       out = (float*)d_out;

    int N  = in_sizes[0] / C;    // 100000
    int E  = in_sizes[1] / 2;    // 1200000
    int CH = (N + NB - 1) / NB;  // 226 <= 256

    k_mega<<<NB, 256>>>(x, ei, W1, b1, W2, b2, out, N, E, CH);
}

// round 12
// speedup vs baseline: 1.5250x; 1.5250x over previous
#include <cuda_runtime.h>
#include <cuda_fp16.h>
#include <stdint.h>

#define NN 100000
#define EMAX 1200000
#define C 64
#define NB_PRE 444   // 3 blocks/SM on 148 SMs -> co-residency guaranteed

// ---------------- scratch (device globals; no allocation allowed) ----------
__device__ __half g_ha[NN * C];    // gemm1 out (prescaled)
__device__ __half g_hb[NN * C];    // fused agg1+gemm2 out (prescaled)
__device__ __half g_w1h[C * C];
__device__ __half g_w2h[C * C];
__device__ float  g_dinv[NN];
__device__ int    g_deg[NN];
__device__ int    g_rowptr[NN];
__device__ int    g_cursor[NN];
__device__ int    g_col[EMAX];
__device__ int    g_total;
__device__ int    g_is64;
__device__ int    g_barA[8];
__device__ int    g_barD[8];

// ---------------- device-wide barrier (self-resetting, replay-safe) ---------
__device__ __forceinline__ void grid_barrier(int slot, int nb) {
    __syncthreads();
    if (threadIdx.x == 0) {
        __threadfence();
        atomicAdd(&g_barA[slot], 1);
        while (atomicAdd(&g_barA[slot], 0) < nb) __nanosleep(64);
        __threadfence();
        int d = atomicAdd(&g_barD[slot], 1);
        if (d == nb - 1) {
            atomicExch(&g_barA[slot], 0);
            atomicExch(&g_barD[slot], 0);
        }
    }
    __syncthreads();
}

__device__ __forceinline__ int blk_excl_scan256(int v, int* tot) {
    __shared__ int ws[8];
    int lane = threadIdx.x & 31, w = threadIdx.x >> 5;
    int x = v;
#pragma unroll
    for (int o = 1; o < 32; o <<= 1) {
        int u = __shfl_up_sync(0xffffffffu, x, o);
        if (lane >= o) x += u;
    }
    if (lane == 31) ws[w] = x;
    __syncthreads();
    if (w == 0) {
        int s = (lane < 8) ? ws[lane] : 0;
#pragma unroll
        for (int o = 1; o < 8; o <<= 1) {
            int u = __shfl_up_sync(0xffffffffu, s, o);
            if (lane >= o) s += u;
        }
        if (lane < 8) ws[lane] = s;
    }
    __syncthreads();
    *tot = ws[7];
    int excl = x - v + (w ? ws[w - 1] : 0);
    __syncthreads();
    return excl;
}

__device__ __forceinline__ int load_idx(const void* eiv, long long pos) {
    if (g_is64) return ((const int*)eiv)[pos << 1];
    return ((const int*)eiv)[pos];
}

// ---------------- persistent preprocessing (3 phases, 2 barriers) -----------
__global__ void __launch_bounds__(256, 4) k_pre(const void* __restrict__ eiv,
                                                const float* __restrict__ W1,
                                                const float* __restrict__ W2,
                                                int E, int N, int CH) {
    int b = blockIdx.x, t = threadIdx.x;
    const int NB = gridDim.x;

    for (int i = b * 256 + t; i < N; i += NB * 256) g_deg[i] = 0;
    if (b == 0) {
        __shared__ int anz;
        if (t == 0) { anz = 0; g_total = 0; }
        __syncthreads();
        int e = t * (E / 256);
        if (((const int*)eiv)[2 * e + 1] != 0) anz = 1;
        __syncthreads();
        if (t == 0) g_is64 = (anz == 0);
    }
    if (b == 1 || b == 2) {
        const float* Wsrc = (b == 2) ? W2 : W1;
        __half* Wdst = (b == 2) ? g_w2h : g_w1h;
        const float4* W4 = (const float4*)Wsrc;
#pragma unroll
        for (int i = 0; i < 4; i++) {
            int j = t + 256 * i;
            float4 v = W4[j];
            __half2 h0 = __floats2half2_rn(v.x, v.y);
            __half2 h1 = __floats2half2_rn(v.z, v.w);
            *(uint2*)&Wdst[j * 4] = make_uint2(*(uint32_t*)&h0, *(uint32_t*)&h1);
        }
    }
    grid_barrier(0, NB);

    for (int e = b * 256 + t; e < E; e += NB * 256) {
        int d = load_idx(eiv, (long long)E + e);
        if ((unsigned)d < (unsigned)NN) atomicAdd(&g_deg[d], 1);
    }
    grid_barrier(1, NB);

    {
        __shared__ int base;
        int i = b * CH + t;
        bool ok = (t < CH && i < N);
        int v = ok ? g_deg[i] : 0;
        int tot;
        int ex = blk_excl_scan256(v, &tot);
        if (t == 0) base = atomicAdd(&g_total, tot);
        __syncthreads();
        if (ok) {
            int r = base + ex;
            g_rowptr[i] = r;
            g_cursor[i] = r;
            g_dinv[i]   = rsqrtf((float)(v + 1));
        }
    }
}

__device__ __forceinline__ void scatter_body(const void* eiv, int E, int bid) {
    int e = bid * 256 + threadIdx.x;
    if (e < E) {
        int s = load_idx(eiv, e);
        int d = load_idx(eiv, (long long)E + e);
        if ((unsigned)s < (unsigned)NN && (unsigned)d < (unsigned)NN) {
            int p = atomicAdd(&g_cursor[d], 1);
            g_col[p] = s;
        }
    }
}

// ---------------- tensor-core GEMM pieces ------------------------------------
#define AS_STR 72

__device__ __forceinline__ void ldsm4(uint32_t& r0, uint32_t& r1,
                                      uint32_t& r2, uint32_t& r3, uint32_t a) {
    asm volatile("ldmatrix.sync.aligned.m8n8.x4.shared.b16 {%0,%1,%2,%3}, [%4];"
                 : "=r"(r0), "=r"(r1), "=r"(r2), "=r"(r3) : "r"(a));
}
__device__ __forceinline__ void ldsm4t(uint32_t& r0, uint32_t& r1,
                                       uint32_t& r2, uint32_t& r3, uint32_t a) {
    asm volatile("ldmatrix.sync.aligned.m8n8.x4.trans.shared.b16 {%0,%1,%2,%3}, [%4];"
                 : "=r"(r0), "=r"(r1), "=r"(r2), "=r"(r3) : "r"(a));
}
__device__ __forceinline__ void mma16816(float* d, uint32_t a0, uint32_t a1,
                                         uint32_t a2, uint32_t a3,
                                         uint32_t b0, uint32_t b1) {
    asm volatile(
        "mma.sync.aligned.m16n8k16.row.col.f32.f16.f16.f32 "
        "{%0,%1,%2,%3}, {%4,%5,%6,%7}, {%8,%9}, {%0,%1,%2,%3};"
        : "+f"(d[0]), "+f"(d[1]), "+f"(d[2]), "+f"(d[3])
        : "r"(a0), "r"(a1), "r"(a2), "r"(a3), "r"(b0), "r"(b1));
}

// mma mainloop + prescaled epilogue reading A from smem, writing H
__device__ __forceinline__ void mma_and_store(__half* As, __half* Wsm,
                                              __half* __restrict__ H,
                                              int row0, int N, int tid) {
    int w    = tid >> 5;
    int lane = tid & 31;
    int R    = w * 16;
    int l8   = lane & 7;
    int mb0  = (lane >> 3) & 1;
    int mb1  = (lane >> 4) & 1;

    float d[8][4];
#pragma unroll
    for (int i = 0; i < 8; i++)
#pragma unroll
        for (int j = 0; j < 4; j++) d[i][j] = 0.f;

    uint32_t a_base = (uint32_t)__cvta_generic_to_shared(As);
    uint32_t w_base = (uint32_t)__cvta_generic_to_shared(Wsm);

#pragma unroll
    for (int kk = 0; kk < 4; kk++) {
        uint32_t a0, a1, a2, a3;
        uint32_t aaddr = a_base +
            ((R + mb0 * 8 + l8) * AS_STR + kk * 16 + mb1 * 8) * 2;
        ldsm4(a0, a1, a2, a3, aaddr);
#pragma unroll
        for (int np = 0; np < 4; np++) {
            uint32_t b0, b1, b2, b3;
            uint32_t baddr = w_base +
                ((kk * 16 + mb0 * 8 + l8) * AS_STR + np * 16 + mb1 * 8) * 2;
            ldsm4t(b0, b1, b2, b3, baddr);
            mma16816(d[np * 2],     a0, a1, a2, a3, b0, b1);
            mma16816(d[np * 2 + 1], a0, a1, a2, a3, b2, b3);
        }
    }

    int g4 = lane >> 2, t4 = lane & 3;
    int r0g = row0 + R + g4;
    int r1g = r0g + 8;
    float dn0 = (r0g < N) ? g_dinv[r0g] : 0.f;
    float dn1 = (r1g < N) ? g_dinv[r1g] : 0.f;
#pragma unroll
    for (int nt = 0; nt < 8; nt++) {
        int coff = nt * 8 + t4 * 2;
        if (r0g < N)
            *(__half2*)(H + (size_t)r0g * C + coff) =
                __floats2half2_rn(d[nt][0] * dn0, d[nt][1] * dn0);
        if (r1g < N)
            *(__half2*)(H + (size_t)r1g * C + coff) =
                __floats2half2_rn(d[nt][2] * dn1, d[nt][3] * dn1);
    }
}

__device__ __forceinline__ void load_w_smem(const __half* __restrict__ Wh,
                                            __half* Wsm, int tid) {
    const uint4* W8 = (const uint4*)Wh;
#pragma unroll
    for (int i = 0; i < 2; i++) {
        int j = tid + 256 * i;
        int r = j >> 3, c = (j & 7) * 8;
        *(uint4*)&Wsm[r * AS_STR + c] = W8[j];
    }
}

// GEMM1 body (X fp32 -> ha), used in the scatter-fused launch
__device__ __forceinline__ void gemm1_body(const float* __restrict__ X,
                                           __half* __restrict__ H, int N,
                                           int bid) {
    __shared__ __half As[128 * AS_STR];
    __shared__ __half Wsm[64 * AS_STR];
    int tid  = threadIdx.x;
    int row0 = bid * 128;

    load_w_smem(g_w1h, Wsm, tid);
    const float4* X4 = (const float4*)(X + (size_t)row0 * C);
#pragma unroll
    for (int i = 0; i < 8; i++) {
        int j = tid + 256 * i;
        int r = j >> 4, c = (j & 15) * 4;
        float4 v = make_float4(0.f, 0.f, 0.f, 0.f);
        if (row0 + r < N) v = X4[j];
        *(__half2*)&As[r * AS_STR + c]     = __floats2half2_rn(v.x, v.y);
        *(__half2*)&As[r * AS_STR + c + 2] = __floats2half2_rn(v.z, v.w);
    }
    __syncthreads();
    mma_and_store(As, Wsm, H, row0, N, tid);
}

__global__ void __launch_bounds__(256) k_gemm_scatter(
        const float* __restrict__ X, __half* __restrict__ H, int N,
        const void* __restrict__ eiv, int E, int SB) {
    if (blockIdx.x < SB) scatter_body(eiv, E, blockIdx.x);
    else                 gemm1_body(X, H, N, blockIdx.x - SB);
}

// ---------------- FUSED agg1 + GEMM2 -----------------------------------------
// Block handles 128 nodes: 4 passes of (8 warps x 4 nodes) aggregation with
// bias+ReLU, fp16 result written into the GEMM A-tile in smem; then mma with
// W2 and prescaled store to hb. Reads ha, writes hb (distinct -> race-free).
__global__ void __launch_bounds__(256) k_agg_gemm(
        const __half* __restrict__ Hin, const float* __restrict__ bias,
        __half* __restrict__ Hout, int N) {
    __shared__ __half As[128 * AS_STR];
    __shared__ __half Wsm[64 * AS_STR];
    const unsigned F = 0xffffffffu;
    int tid  = threadIdx.x;
    int row0 = blockIdx.x * 128;

    load_w_smem(g_w2h, Wsm, tid);

    int warp = tid >> 5;
    int lane = tid & 31;
    int g    = lane >> 3;
    int l8   = lane & 7;

#pragma unroll
    for (int pass = 0; pass < 4; pass++) {
        int n   = row0 + pass * 32 + warp * 4 + g;
        bool act = (n < N);

        int beg = 0, len = 0;
        if (act) { beg = g_rowptr[n]; len = g_deg[n]; }
        int lm = len;
        lm = max(lm, __shfl_xor_sync(F, lm, 8));
        lm = max(lm, __shfl_xor_sync(F, lm, 16));

        float a0=0.f,a1=0.f,a2=0.f,a3=0.f,a4=0.f,a5=0.f,a6=0.f,a7=0.f;
        for (int off = 0; off < lm; off += 8) {
            int cnt = min(len - off, 8);
            int sp  = (l8 < cnt) ? g_col[beg + off + l8] : 0;
            int cm  = cnt;
            cm = max(cm, __shfl_xor_sync(F, cm, 8));
            cm = max(cm, __shfl_xor_sync(F, cm, 16));
#pragma unroll 4
            for (int j = 0; j < cm; j++) {
                int   s = __shfl_sync(F, sp, (g << 3) + j);
                float m = (j < cnt) ? 1.f : 0.f;
                uint4 v = *(const uint4*)(Hin + (size_t)s * C + l8 * 8);
                float2 f0 = __half22float2(*(__half2*)&v.x);
                float2 f1 = __half22float2(*(__half2*)&v.y);
                float2 f2 = __half22float2(*(__half2*)&v.z);
                float2 f3 = __half22float2(*(__half2*)&v.w);
                a0 += m * f0.x; a1 += m * f0.y; a2 += m * f1.x; a3 += m * f1.y;
                a4 += m * f2.x; a5 += m * f2.y; a6 += m * f3.x; a7 += m * f3.y;
            }
        }

        uint4 pk = make_uint4(0, 0, 0, 0);
        if (act) {
            float dn = g_dinv[n];
            uint4 hv = *(const uint4*)(Hin + (size_t)n * C + l8 * 8);
            float2 h0 = __half22float2(*(__half2*)&hv.x);
            float2 h1 = __half22float2(*(__half2*)&hv.y);
            float2 h2 = __half22float2(*(__half2*)&hv.z);
            float2 h3 = __half22float2(*(__half2*)&hv.w);
            float4 bA = *(const float4*)(bias + l8 * 8);
            float4 bB = *(const float4*)(bias + l8 * 8 + 4);
            float r0 = fmaxf(dn * (a0 + h0.x) + bA.x, 0.f);
            float r1 = fmaxf(dn * (a1 + h0.y) + bA.y, 0.f);
            float r2 = fmaxf(dn * (a2 + h1.x) + bA.z, 0.f);
            float r3 = fmaxf(dn * (a3 + h1.y) + bA.w, 0.f);
            float r4 = fmaxf(dn * (a4 + h2.x) + bB.x, 0.f);
            float r5 = fmaxf(dn * (a5 + h2.y) + bB.y, 0.f);
            float r6 = fmaxf(dn * (a6 + h3.x) + bB.z, 0.f);
            float r7 = fmaxf(dn * (a7 + h3.y) + bB.w, 0.f);
            __half2 o0 = __floats2half2_rn(r0, r1);
            __half2 o1 = __floats2half2_rn(r2, r3);
            __half2 o2 = __floats2half2_rn(r4, r5);
            __half2 o3 = __floats2half2_rn(r6, r7);
            pk = make_uint4(*(uint32_t*)&o0, *(uint32_t*)&o1,
                            *(uint32_t*)&o2, *(uint32_t*)&o3);
        }
        int lr = pass * 32 + warp * 4 + g;     // local row in tile
        *(uint4*)&As[lr * AS_STR + l8 * 8] = pk;
    }
    __syncthreads();

    mma_and_store(As, Wsm, Hout, row0, N, tid);
}

// ---------------- final aggregation (fp32 out, no relu) ----------------------
__global__ void __launch_bounds__(256) k_agg_out(const __half* __restrict__ H,
                                                 const float* __restrict__ bias,
                                                 float* __restrict__ out, int N) {
    const unsigned F = 0xffffffffu;
    int gid  = blockIdx.x * blockDim.x + threadIdx.x;
    int warp = gid >> 5;
    int lane = gid & 31;
    int g    = lane >> 3;
    int l8   = lane & 7;
    int n    = warp * 4 + g;
    bool act = (n < N);

    int beg = 0, len = 0;
    if (act) { beg = g_rowptr[n]; len = g_deg[n]; }
    int lm = len;
    lm = max(lm, __shfl_xor_sync(F, lm, 8));
    lm = max(lm, __shfl_xor_sync(F, lm, 16));

    float a0=0.f,a1=0.f,a2=0.f,a3=0.f,a4=0.f,a5=0.f,a6=0.f,a7=0.f;
    for (int off = 0; off < lm; off += 8) {
        int cnt = min(len - off, 8);
        int sp  = (l8 < cnt) ? g_col[beg + off + l8] : 0;
        int cm  = cnt;
        cm = max(cm, __shfl_xor_sync(F, cm, 8));
        cm = max(cm, __shfl_xor_sync(F, cm, 16));
#pragma unroll 4
        for (int j = 0; j < cm; j++) {
            int   s = __shfl_sync(F, sp, (g << 3) + j);
            float m = (j < cnt) ? 1.f : 0.f;
            uint4 v = *(const uint4*)(H + (size_t)s * C + l8 * 8);
            float2 f0 = __half22float2(*(__half2*)&v.x);
            float2 f1 = __half22float2(*(__half2*)&v.y);
            float2 f2 = __half22float2(*(__half2*)&v.z);
            float2 f3 = __half22float2(*(__half2*)&v.w);
            a0 += m * f0.x; a1 += m * f0.y; a2 += m * f1.x; a3 += m * f1.y;
            a4 += m * f2.x; a5 += m * f2.y; a6 += m * f3.x; a7 += m * f3.y;
        }
    }

    if (act) {
        float dn = g_dinv[n];
        uint4 hv = *(const uint4*)(H + (size_t)n * C + l8 * 8);
        float2 h0 = __half22float2(*(__half2*)&hv.x);
        float2 h1 = __half22float2(*(__half2*)&hv.y);
        float2 h2 = __half22float2(*(__half2*)&hv.z);
        float2 h3 = __half22float2(*(__half2*)&hv.w);
        float4 bA = *(const float4*)(bias + l8 * 8);
        float4 bB = *(const float4*)(bias + l8 * 8 + 4);
        float* o = out + (size_t)n * C + l8 * 8;
        *(float4*)o = make_float4(dn * (a0 + h0.x) + bA.x,
                                  dn * (a1 + h0.y) + bA.y,
                                  dn * (a2 + h1.x) + bA.z,
                                  dn * (a3 + h1.y) + bA.w);
        *(float4*)(o + 4) = make_float4(dn * (a4 + h2.x) + bB.x,
                                        dn * (a5 + h2.y) + bB.y,
                                        dn * (a6 + h3.x) + bB.z,
                                        dn * (a7 + h3.y) + bB.w);
    }
}

// ---------------- launch ------------------------------------------------------
extern "C" void kernel_launch(void* const* d_in, const int* in_sizes, int n_in,
                              void* d_out, int out_size) {
    const float* x   = (const float*)d_in[0];
    const void*  ei  = d_in[1];
    const float* W1  = (const float*)d_in[2];
    const float* b1  = (const float*)d_in[3];
    const float* W2  = (const float*)d_in[4];
    const float* b2  = (const float*)d_in[5];
    float*       out = (float*)d_out;

    int N = in_sizes[0] / C;     // 100000
    int E = in_sizes[1] / 2;     // 1200000

    __half* ha; cudaGetSymbolAddress((void**)&ha, g_ha);
    __half* hb; cudaGetSymbolAddress((void**)&hb, g_hb);

    int CH  = (N + NB_PRE - 1) / NB_PRE;
    int SB  = (E + 255) / 256;
    int GB  = (N + 127) / 128;   // 782
    int AGB = (N + 31) / 32;

    k_pre<<<NB_PRE, 256>>>(ei, W1, W2, E, N, CH);
    k_gemm_scatter<<<SB + GB, 256>>>(x, ha, N, ei, E, SB);
    k_agg_gemm<<<GB, 256>>>(ha, b1, hb, N);
    k_agg_out<<<AGB, 256>>>(hb, b2, out, N);
}

// round 13
// speedup vs baseline: 1.6176x; 1.0607x over previous
#include <cuda_runtime.h>
#include <cuda_fp16.h>
#include <stdint.h>

#define NN 100000
#define EMAX 1200000
#define C 64
#define NB_PRE 444   // 3 blocks/SM on 148 SMs -> co-residency guaranteed

// ---------------- scratch (device globals; no allocation allowed) ----------
__device__ __half g_ha[NN * C];
__device__ __half g_hb[NN * C];
__device__ __half g_w1h[C * C];
__device__ __half g_w2h[C * C];
__device__ float  g_dinv[NN];
__device__ int    g_deg[NN];
__device__ int    g_rowptr[NN];
__device__ int    g_cursor[NN];
__device__ int    g_col[EMAX];
__device__ int    g_total;
__device__ int    g_is64;
__device__ int    g_barA[8];
__device__ int    g_barD[8];

// ---------------- device-wide barrier (self-resetting, replay-safe) ---------
__device__ __forceinline__ void grid_barrier(int slot, int nb) {
    __syncthreads();
    if (threadIdx.x == 0) {
        __threadfence();
        atomicAdd(&g_barA[slot], 1);
        while (atomicAdd(&g_barA[slot], 0) < nb) __nanosleep(64);
        __threadfence();
        int d = atomicAdd(&g_barD[slot], 1);
        if (d == nb - 1) {
            atomicExch(&g_barA[slot], 0);
            atomicExch(&g_barD[slot], 0);
        }
    }
    __syncthreads();
}

__device__ __forceinline__ int blk_excl_scan256(int v, int* tot) {
    __shared__ int ws[8];
    int lane = threadIdx.x & 31, w = threadIdx.x >> 5;
    int x = v;
#pragma unroll
    for (int o = 1; o < 32; o <<= 1) {
        int u = __shfl_up_sync(0xffffffffu, x, o);
        if (lane >= o) x += u;
    }
    if (lane == 31) ws[w] = x;
    __syncthreads();
    if (w == 0) {
        int s = (lane < 8) ? ws[lane] : 0;
#pragma unroll
        for (int o = 1; o < 8; o <<= 1) {
            int u = __shfl_up_sync(0xffffffffu, s, o);
            if (lane >= o) s += u;
        }
        if (lane < 8) ws[lane] = s;
    }
    __syncthreads();
    *tot = ws[7];
    int excl = x - v + (w ? ws[w - 1] : 0);
    __syncthreads();
    return excl;
}

__device__ __forceinline__ int load_idx(const void* eiv, long long pos) {
    if (g_is64) return ((const int*)eiv)[pos << 1];
    return ((const int*)eiv)[pos];
}

// ---------------- persistent preprocessing (3 phases, 2 barriers) -----------
__global__ void __launch_bounds__(256, 4) k_pre(const void* __restrict__ eiv,
                                                const float* __restrict__ W1,
                                                const float* __restrict__ W2,
                                                int E, int N, int CH) {
    int b = blockIdx.x, t = threadIdx.x;
    const int NB = gridDim.x;

    for (int i = b * 256 + t; i < N; i += NB * 256) g_deg[i] = 0;
    if (b == 0) {
        __shared__ int anz;
        if (t == 0) { anz = 0; g_total = 0; }
        __syncthreads();
        int e = t * (E / 256);
        if (((const int*)eiv)[2 * e + 1] != 0) anz = 1;
        __syncthreads();
        if (t == 0) g_is64 = (anz == 0);
    }
    if (b == 1 || b == 2) {
        const float* Wsrc = (b == 2) ? W2 : W1;
        __half* Wdst = (b == 2) ? g_w2h : g_w1h;
        const float4* W4 = (const float4*)Wsrc;
#pragma unroll
        for (int i = 0; i < 4; i++) {
            int j = t + 256 * i;
            float4 v = W4[j];
            __half2 h0 = __floats2half2_rn(v.x, v.y);
            __half2 h1 = __floats2half2_rn(v.z, v.w);
            *(uint2*)&Wdst[j * 4] = make_uint2(*(uint32_t*)&h0, *(uint32_t*)&h1);
        }
    }
    grid_barrier(0, NB);

    for (int e = b * 256 + t; e < E; e += NB * 256) {
        int d = load_idx(eiv, (long long)E + e);
        if ((unsigned)d < (unsigned)NN) atomicAdd(&g_deg[d], 1);
    }
    grid_barrier(1, NB);

    {
        __shared__ int base;
        int i = b * CH + t;
        bool ok = (t < CH && i < N);
        int v = ok ? g_deg[i] : 0;
        int tot;
        int ex = blk_excl_scan256(v, &tot);
        if (t == 0) base = atomicAdd(&g_total, tot);
        __syncthreads();
        if (ok) {
            int r = base + ex;
            g_rowptr[i] = r;
            g_cursor[i] = r;
            g_dinv[i]   = rsqrtf((float)(v + 1));
        }
    }
}

__device__ __forceinline__ void scatter_body(const void* eiv, int E, int bid) {
    int e = bid * 256 + threadIdx.x;
    if (e < E) {
        int s = load_idx(eiv, e);
        int d = load_idx(eiv, (long long)E + e);
        if ((unsigned)s < (unsigned)NN && (unsigned)d < (unsigned)NN) {
            int p = atomicAdd(&g_cursor[d], 1);
            g_col[p] = s;
        }
    }
}

// ---------------- tensor-core GEMM pieces ------------------------------------
#define AS_STR 72

__device__ __forceinline__ void ldsm4(uint32_t& r0, uint32_t& r1,
                                      uint32_t& r2, uint32_t& r3, uint32_t a) {
    asm volatile("ldmatrix.sync.aligned.m8n8.x4.shared.b16 {%0,%1,%2,%3}, [%4];"
                 : "=r"(r0), "=r"(r1), "=r"(r2), "=r"(r3) : "r"(a));
}
__device__ __forceinline__ void ldsm4t(uint32_t& r0, uint32_t& r1,
                                       uint32_t& r2, uint32_t& r3, uint32_t a) {
    asm volatile("ldmatrix.sync.aligned.m8n8.x4.trans.shared.b16 {%0,%1,%2,%3}, [%4];"
                 : "=r"(r0), "=r"(r1), "=r"(r2), "=r"(r3) : "r"(a));
}
__device__ __forceinline__ void mma16816(float* d, uint32_t a0, uint32_t a1,
                                         uint32_t a2, uint32_t a3,
                                         uint32_t b0, uint32_t b1) {
    asm volatile(
        "mma.sync.aligned.m16n8k16.row.col.f32.f16.f16.f32 "
        "{%0,%1,%2,%3}, {%4,%5,%6,%7}, {%8,%9}, {%0,%1,%2,%3};"
        : "+f"(d[0]), "+f"(d[1]), "+f"(d[2]), "+f"(d[3])
        : "r"(a0), "r"(a1), "r"(a2), "r"(a3), "r"(b0), "r"(b1));
}

__device__ __forceinline__ void load_a_tile(const float* __restrict__ X,
                                            __half* As, int row0, int N, int tid) {
    const float4* X4 = (const float4*)(X + (size_t)row0 * C);
#pragma unroll
    for (int i = 0; i < 8; i++) {
        int j = tid + 256 * i;
        int r = j >> 4, c = (j & 15) * 4;
        float4 v = make_float4(0.f, 0.f, 0.f, 0.f);
        if (row0 + r < N) v = X4[j];
        *(__half2*)&As[r * AS_STR + c]     = __floats2half2_rn(v.x, v.y);
        *(__half2*)&As[r * AS_STR + c + 2] = __floats2half2_rn(v.z, v.w);
    }
}
__device__ __forceinline__ void load_a_tile(const __half* __restrict__ X,
                                            __half* As, int row0, int N, int tid) {
    const uint4* X8 = (const uint4*)(X + (size_t)row0 * C);
#pragma unroll
    for (int i = 0; i < 4; i++) {
        int j = tid + 256 * i;
        int r = j >> 3, c = (j & 7) * 8;
        uint4 v = make_uint4(0, 0, 0, 0);
        if (row0 + r < N) v = X8[j];
        *(uint4*)&As[r * AS_STR + c] = v;
    }
}

template <typename T>
__device__ __forceinline__ void gemm_body(const T* __restrict__ X,
                                          const __half* __restrict__ Wh,
                                          __half* __restrict__ H, int N,
                                          int bid) {
    __shared__ __half As[128 * AS_STR];
    __shared__ __half Wsm[64 * AS_STR];
    int tid  = threadIdx.x;
    int row0 = bid * 128;

    {
        const uint4* W8 = (const uint4*)Wh;
#pragma unroll
        for (int i = 0; i < 2; i++) {
            int j = tid + 256 * i;
            int r = j >> 3, c = (j & 7) * 8;
            *(uint4*)&Wsm[r * AS_STR + c] = W8[j];
        }
    }
    load_a_tile(X, As, row0, N, tid);
    __syncthreads();

    int w    = tid >> 5;
    int lane = tid & 31;
    int R    = w * 16;
    int l8   = lane & 7;
    int mb0  = (lane >> 3) & 1;
    int mb1  = (lane >> 4) & 1;

    float d[8][4];
#pragma unroll
    for (int i = 0; i < 8; i++)
#pragma unroll
        for (int j = 0; j < 4; j++) d[i][j] = 0.f;

    uint32_t a_base = (uint32_t)__cvta_generic_to_shared(As);
    uint32_t w_base = (uint32_t)__cvta_generic_to_shared(Wsm);

#pragma unroll
    for (int kk = 0; kk < 4; kk++) {
        uint32_t a0, a1, a2, a3;
        uint32_t aaddr = a_base +
            ((R + mb0 * 8 + l8) * AS_STR + kk * 16 + mb1 * 8) * 2;
        ldsm4(a0, a1, a2, a3, aaddr);
#pragma unroll
        for (int np = 0; np < 4; np++) {
            uint32_t b0, b1, b2, b3;
            uint32_t baddr = w_base +
                ((kk * 16 + mb0 * 8 + l8) * AS_STR + np * 16 + mb1 * 8) * 2;
            ldsm4t(b0, b1, b2, b3, baddr);
            mma16816(d[np * 2],     a0, a1, a2, a3, b0, b1);
            mma16816(d[np * 2 + 1], a0, a1, a2, a3, b2, b3);
        }
    }

    int g4 = lane >> 2, t4 = lane & 3;
    int r0g = row0 + R + g4;
    int r1g = r0g + 8;
    float dn0 = (r0g < N) ? g_dinv[r0g] : 0.f;
    float dn1 = (r1g < N) ? g_dinv[r1g] : 0.f;
#pragma unroll
    for (int nt = 0; nt < 8; nt++) {
        int coff = nt * 8 + t4 * 2;
        if (r0g < N)
            *(__half2*)(H + (size_t)r0g * C + coff) =
                __floats2half2_rn(d[nt][0] * dn0, d[nt][1] * dn0);
        if (r1g < N)
            *(__half2*)(H + (size_t)r1g * C + coff) =
                __floats2half2_rn(d[nt][2] * dn1, d[nt][3] * dn1);
    }
}

__global__ void __launch_bounds__(256) k_gemm_h(const __half* __restrict__ X,
                                                const __half* __restrict__ Wh,
                                                __half* __restrict__ H, int N) {
    gemm_body<__half>(X, Wh, H, N, blockIdx.x);
}

__global__ void __launch_bounds__(256) k_gemm_scatter(
        const float* __restrict__ X, const __half* __restrict__ Wh,
        __half* __restrict__ H, int N,
        const void* __restrict__ eiv, int E, int SB) {
    if (blockIdx.x < SB) scatter_body(eiv, E, blockIdx.x);
    else                 gemm_body<float>(X, Wh, H, N, blockIdx.x - SB);
}

// ---------------- aggregation: fp16 HFMA2 accumulation -----------------------
// 4 nodes per warp (8-lane groups). Messages accumulated in TWO interleaved
// fp16 accumulators (even/odd edge) -> chain length ~deg/2; combined in fp32.
// Self-term, dinv scale and bias stay fp32.
template <bool HALF_OUT, bool RELU>
__global__ void __launch_bounds__(256) k_agg(const __half* __restrict__ H,
                                             const float* __restrict__ bias,
                                             void* __restrict__ outv, int N) {
    const unsigned F = 0xffffffffu;
    int gid  = blockIdx.x * blockDim.x + threadIdx.x;
    int warp = gid >> 5;
    int lane = gid & 31;
    int g    = lane >> 3;
    int l8   = lane & 7;
    int n    = warp * 4 + g;
    bool act = (n < N);

    int beg = 0, len = 0;
    if (act) { beg = g_rowptr[n]; len = g_deg[n]; }
    int lm = len;
    lm = max(lm, __shfl_xor_sync(F, lm, 8));
    lm = max(lm, __shfl_xor_sync(F, lm, 16));

    const uint32_t ONE2  = 0x3C003C00u;   // half2(1,1)
    __half2 A0[4], A1[4];
#pragma unroll
    for (int i = 0; i < 4; i++) {
        A0[i] = __floats2half2_rn(0.f, 0.f);
        A1[i] = __floats2half2_rn(0.f, 0.f);
    }

    for (int off = 0; off < lm; off += 8) {
        int cnt = min(len - off, 8);
        int sp  = (l8 < cnt) ? g_col[beg + off + l8] : 0;
        int cm  = cnt;
        cm = max(cm, __shfl_xor_sync(F, cm, 8));
        cm = max(cm, __shfl_xor_sync(F, cm, 16));
#pragma unroll 4
        for (int j = 0; j < cm; j++) {
            int s = __shfl_sync(F, sp, (g << 3) + j);
            uint32_t mbits = (j < cnt) ? ONE2 : 0u;
            __half2 m2 = *(__half2*)&mbits;
            uint4 v = *(const uint4*)(H + (size_t)s * C + l8 * 8);
            __half2* vh = (__half2*)&v;
            if (j & 1) {
                A1[0] = __hfma2(vh[0], m2, A1[0]);
                A1[1] = __hfma2(vh[1], m2, A1[1]);
                A1[2] = __hfma2(vh[2], m2, A1[2]);
                A1[3] = __hfma2(vh[3], m2, A1[3]);
            } else {
                A0[0] = __hfma2(vh[0], m2, A0[0]);
                A0[1] = __hfma2(vh[1], m2, A0[1]);
                A0[2] = __hfma2(vh[2], m2, A0[2]);
                A0[3] = __hfma2(vh[3], m2, A0[3]);
            }
        }
    }

    if (act) {
        float2 e0 = __half22float2(A0[0]), o0 = __half22float2(A1[0]);
        float2 e1 = __half22float2(A0[1]), o1 = __half22float2(A1[1]);
        float2 e2 = __half22float2(A0[2]), o2 = __half22float2(A1[2]);
        float2 e3 = __half22float2(A0[3]), o3 = __half22float2(A1[3]);
        float a0 = e0.x + o0.x, a1 = e0.y + o0.y;
        float a2 = e1.x + o1.x, a3 = e1.y + o1.y;
        float a4 = e2.x + o2.x, a5 = e2.y + o2.y;
        float a6 = e3.x + o3.x, a7 = e3.y + o3.y;

        float dn = g_dinv[n];
        uint4 hv = *(const uint4*)(H + (size_t)n * C + l8 * 8);
        float2 h0 = __half22float2(*(__half2*)&hv.x);
        float2 h1 = __half22float2(*(__half2*)&hv.y);
        float2 h2 = __half22float2(*(__half2*)&hv.z);
        float2 h3 = __half22float2(*(__half2*)&hv.w);
        float4 bA = *(const float4*)(bias + l8 * 8);
        float4 bB = *(const float4*)(bias + l8 * 8 + 4);
        float r0 = dn * (a0 + h0.x) + bA.x;
        float r1 = dn * (a1 + h0.y) + bA.y;
        float r2 = dn * (a2 + h1.x) + bA.z;
        float r3 = dn * (a3 + h1.y) + bA.w;
        float r4 = dn * (a4 + h2.x) + bB.x;
        float r5 = dn * (a5 + h2.y) + bB.y;
        float r6 = dn * (a6 + h3.x) + bB.z;
        float r7 = dn * (a7 + h3.y) + bB.w;
        if (RELU) {
            r0 = fmaxf(r0, 0.f); r1 = fmaxf(r1, 0.f);
            r2 = fmaxf(r2, 0.f); r3 = fmaxf(r3, 0.f);
            r4 = fmaxf(r4, 0.f); r5 = fmaxf(r5, 0.f);
            r6 = fmaxf(r6, 0.f); r7 = fmaxf(r7, 0.f);
        }
        if (HALF_OUT) {
            __half2 q0 = __floats2half2_rn(r0, r1);
            __half2 q1 = __floats2half2_rn(r2, r3);
            __half2 q2 = __floats2half2_rn(r4, r5);
            __half2 q3 = __floats2half2_rn(r6, r7);
            uint4 pk = make_uint4(*(uint32_t*)&q0, *(uint32_t*)&q1,
                                  *(uint32_t*)&q2, *(uint32_t*)&q3);
            *(uint4*)((__half*)outv + (size_t)n * C + l8 * 8) = pk;
        } else {
            float* o = (float*)outv + (size_t)n * C + l8 * 8;
            *(float4*)o       = make_float4(r0, r1, r2, r3);
            *(float4*)(o + 4) = make_float4(r4, r5, r6, r7);
        }
    }
}

// ---------------- launch ------------------------------------------------------
extern "C" void kernel_launch(void* const* d_in, const int* in_sizes, int n_in,
                              void* d_out, int out_size) {
    const float* x   = (const float*)d_in[0];
    const void*  ei  = d_in[1];
    const float* W1  = (const float*)d_in[2];
    const float* b1  = (const float*)d_in[3];
    const float* W2  = (const float*)d_in[4];
    const float* b2  = (const float*)d_in[5];
    float*       out = (float*)d_out;

    int N = in_sizes[0] / C;     // 100000
    int E = in_sizes[1] / 2;     // 1200000

    __half* ha;  cudaGetSymbolAddress((void**)&ha, g_ha);
    __half* hb;  cudaGetSymbolAddress((void**)&hb, g_hb);
    __half* w1h; cudaGetSymbolAddress((void**)&w1h, g_w1h);
    __half* w2h; cudaGetSymbolAddress((void**)&w2h, g_w2h);

    int CH  = (N + NB_PRE - 1) / NB_PRE;
    int SB  = (E + 255) / 256;
    int GB  = (N + 127) / 128;
    int AGB = (N + 31) / 32;

    k_pre<<<NB_PRE, 256>>>(ei, W1, W2, E, N, CH);
    k_gemm_scatter<<<SB + GB, 256>>>(x, w1h, ha, N, ei, E, SB);
    k_agg<true, true><<<AGB, 256>>>(ha, b1, hb, N);
    k_gemm_h<<<GB, 256>>>(hb, w2h, ha, N);
    k_agg<false, false><<<AGB, 256>>>(ha, b2, out, N);
}

// round 14
// speedup vs baseline: 1.6224x; 1.0030x over previous
#include <cuda_runtime.h>
#include <cuda_fp16.h>
#include <stdint.h>

#define NN 100000
#define EMAX 1200000
#define C 64
#define NB_PRE 444   // 3 blocks/SM on 148 SMs -> co-residency guaranteed

// ---------------- scratch (device globals; no allocation allowed) ----------
__device__ __half g_ha[NN * C];
__device__ __half g_hb[NN * C];
__device__ __half g_w1h[C * C];
__device__ __half g_w2h[C * C];
__device__ float  g_dinv[NN];
__device__ int    g_deg[NN];
__device__ int    g_rowptr[NN];
__device__ int    g_cursor[NN];
__device__ int    g_col[EMAX];
__device__ int    g_total;
__device__ int    g_is64;
__device__ int    g_barA[8];
__device__ int    g_barD[8];

// ---------------- device-wide barrier (self-resetting, replay-safe) ---------
__device__ __forceinline__ void grid_barrier(int slot, int nb) {
    __syncthreads();
    if (threadIdx.x == 0) {
        __threadfence();
        atomicAdd(&g_barA[slot], 1);
        while (atomicAdd(&g_barA[slot], 0) < nb) __nanosleep(64);
        __threadfence();
        int d = atomicAdd(&g_barD[slot], 1);
        if (d == nb - 1) {
            atomicExch(&g_barA[slot], 0);
            atomicExch(&g_barD[slot], 0);
        }
    }
    __syncthreads();
}

__device__ __forceinline__ int blk_excl_scan256(int v, int* tot) {
    __shared__ int ws[8];
    int lane = threadIdx.x & 31, w = threadIdx.x >> 5;
    int x = v;
#pragma unroll
    for (int o = 1; o < 32; o <<= 1) {
        int u = __shfl_up_sync(0xffffffffu, x, o);
        if (lane >= o) x += u;
    }
    if (lane == 31) ws[w] = x;
    __syncthreads();
    if (w == 0) {
        int s = (lane < 8) ? ws[lane] : 0;
#pragma unroll
        for (int o = 1; o < 8; o <<= 1) {
            int u = __shfl_up_sync(0xffffffffu, s, o);
            if (lane >= o) s += u;
        }
        if (lane < 8) ws[lane] = s;
    }
    __syncthreads();
    *tot = ws[7];
    int excl = x - v + (w ? ws[w - 1] : 0);
    __syncthreads();
    return excl;
}

__device__ __forceinline__ int load_idx(const void* eiv, long long pos) {
    if (g_is64) return ((const int*)eiv)[pos << 1];
    return ((const int*)eiv)[pos];
}

// ---------------- persistent preprocessing (3 phases, 2 barriers) -----------
__global__ void __launch_bounds__(256, 4) k_pre(const void* __restrict__ eiv,
                                                const float* __restrict__ W1,
                                                const float* __restrict__ W2,
                                                int E, int N, int CH) {
    int b = blockIdx.x, t = threadIdx.x;
    const int NB = gridDim.x;

    for (int i = b * 256 + t; i < N; i += NB * 256) g_deg[i] = 0;
    if (b == 0) {
        __shared__ int anz;
        if (t == 0) { anz = 0; g_total = 0; }
        __syncthreads();
        int e = t * (E / 256);
        if (((const int*)eiv)[2 * e + 1] != 0) anz = 1;
        __syncthreads();
        if (t == 0) g_is64 = (anz == 0);
    }
    if (b == 1 || b == 2) {
        const float* Wsrc = (b == 2) ? W2 : W1;
        __half* Wdst = (b == 2) ? g_w2h : g_w1h;
        const float4* W4 = (const float4*)Wsrc;
#pragma unroll
        for (int i = 0; i < 4; i++) {
            int j = t + 256 * i;
            float4 v = W4[j];
            __half2 h0 = __floats2half2_rn(v.x, v.y);
            __half2 h1 = __floats2half2_rn(v.z, v.w);
            *(uint2*)&Wdst[j * 4] = make_uint2(*(uint32_t*)&h0, *(uint32_t*)&h1);
        }
    }
    grid_barrier(0, NB);

    for (int e = b * 256 + t; e < E; e += NB * 256) {
        int d = load_idx(eiv, (long long)E + e);
        if ((unsigned)d < (unsigned)NN) atomicAdd(&g_deg[d], 1);
    }
    grid_barrier(1, NB);

    {
        __shared__ int base;
        int i = b * CH + t;
        bool ok = (t < CH && i < N);
        int v = ok ? g_deg[i] : 0;
        int tot;
        int ex = blk_excl_scan256(v, &tot);
        if (t == 0) base = atomicAdd(&g_total, tot);
        __syncthreads();
        if (ok) {
            int r = base + ex;
            g_rowptr[i] = r;
            g_cursor[i] = r;
            g_dinv[i]   = rsqrtf((float)(v + 1));
        }
    }
}

__device__ __forceinline__ void scatter_body(const void* eiv, int E, int bid) {
    int e = bid * 256 + threadIdx.x;
    if (e < E) {
        int s = load_idx(eiv, e);
        int d = load_idx(eiv, (long long)E + e);
        if ((unsigned)s < (unsigned)NN && (unsigned)d < (unsigned)NN) {
            int p = atomicAdd(&g_cursor[d], 1);
            g_col[p] = s;
        }
    }
}

// ---------------- tensor-core GEMM pieces ------------------------------------
#define AS_STR 72

__device__ __forceinline__ void ldsm4(uint32_t& r0, uint32_t& r1,
                                      uint32_t& r2, uint32_t& r3, uint32_t a) {
    asm volatile("ldmatrix.sync.aligned.m8n8.x4.shared.b16 {%0,%1,%2,%3}, [%4];"
                 : "=r"(r0), "=r"(r1), "=r"(r2), "=r"(r3) : "r"(a));
}
__device__ __forceinline__ void ldsm4t(uint32_t& r0, uint32_t& r1,
                                       uint32_t& r2, uint32_t& r3, uint32_t a) {
    asm volatile("ldmatrix.sync.aligned.m8n8.x4.trans.shared.b16 {%0,%1,%2,%3}, [%4];"
                 : "=r"(r0), "=r"(r1), "=r"(r2), "=r"(r3) : "r"(a));
}
__device__ __forceinline__ void mma16816(float* d, uint32_t a0, uint32_t a1,
                                         uint32_t a2, uint32_t a3,
                                         uint32_t b0, uint32_t b1) {
    asm volatile(
        "mma.sync.aligned.m16n8k16.row.col.f32.f16.f16.f32 "
        "{%0,%1,%2,%3}, {%4,%5,%6,%7}, {%8,%9}, {%0,%1,%2,%3};"
        : "+f"(d[0]), "+f"(d[1]), "+f"(d[2]), "+f"(d[3])
        : "r"(a0), "r"(a1), "r"(a2), "r"(a3), "r"(b0), "r"(b1));
}

__device__ __forceinline__ void load_a_tile(const float* __restrict__ X,
                                            __half* As, int row0, int N, int tid) {
    const float4* X4 = (const float4*)(X + (size_t)row0 * C);
#pragma unroll
    for (int i = 0; i < 8; i++) {
        int j = tid + 256 * i;
        int r = j >> 4, c = (j & 15) * 4;
        float4 v = make_float4(0.f, 0.f, 0.f, 0.f);
        if (row0 + r < N) v = X4[j];
        *(__half2*)&As[r * AS_STR + c]     = __floats2half2_rn(v.x, v.y);
        *(__half2*)&As[r * AS_STR + c + 2] = __floats2half2_rn(v.z, v.w);
    }
}
__device__ __forceinline__ void load_a_tile(const __half* __restrict__ X,
                                            __half* As, int row0, int N, int tid) {
    const uint4* X8 = (const uint4*)(X + (size_t)row0 * C);
#pragma unroll
    for (int i = 0; i < 4; i++) {
        int j = tid + 256 * i;
        int r = j >> 3, c = (j & 7) * 8;
        uint4 v = make_uint4(0, 0, 0, 0);
        if (row0 + r < N) v = X8[j];
        *(uint4*)&As[r * AS_STR + c] = v;
    }
}

template <typename T>
__device__ __forceinline__ void gemm_body(const T* __restrict__ X,
                                          const __half* __restrict__ Wh,
                                          __half* __restrict__ H, int N,
                                          int bid) {
    __shared__ __half As[128 * AS_STR];
    __shared__ __half Wsm[64 * AS_STR];
    int tid  = threadIdx.x;
    int row0 = bid * 128;

    {
        const uint4* W8 = (const uint4*)Wh;
#pragma unroll
        for (int i = 0; i < 2; i++) {
            int j = tid + 256 * i;
            int r = j >> 3, c = (j & 7) * 8;
            *(uint4*)&Wsm[r * AS_STR + c] = W8[j];
        }
    }
    load_a_tile(X, As, row0, N, tid);
    __syncthreads();

    int w    = tid >> 5;
    int lane = tid & 31;
    int R    = w * 16;
    int l8   = lane & 7;
    int mb0  = (lane >> 3) & 1;
    int mb1  = (lane >> 4) & 1;

    float d[8][4];
#pragma unroll
    for (int i = 0; i < 8; i++)
#pragma unroll
        for (int j = 0; j < 4; j++) d[i][j] = 0.f;

    uint32_t a_base = (uint32_t)__cvta_generic_to_shared(As);
    uint32_t w_base = (uint32_t)__cvta_generic_to_shared(Wsm);

#pragma unroll
    for (int kk = 0; kk < 4; kk++) {
        uint32_t a0, a1, a2, a3;
        uint32_t aaddr = a_base +
            ((R + mb0 * 8 + l8) * AS_STR + kk * 16 + mb1 * 8) * 2;
        ldsm4(a0, a1, a2, a3, aaddr);
#pragma unroll
        for (int np = 0; np < 4; np++) {
            uint32_t b0, b1, b2, b3;
            uint32_t baddr = w_base +
                ((kk * 16 + mb0 * 8 + l8) * AS_STR + np * 16 + mb1 * 8) * 2;
            ldsm4t(b0, b1, b2, b3, baddr);
            mma16816(d[np * 2],     a0, a1, a2, a3, b0, b1);
            mma16816(d[np * 2 + 1], a0, a1, a2, a3, b2, b3);
        }
    }

    int g4 = lane >> 2, t4 = lane & 3;
    int r0g = row0 + R + g4;
    int r1g = r0g + 8;
    float dn0 = (r0g < N) ? g_dinv[r0g] : 0.f;
    float dn1 = (r1g < N) ? g_dinv[r1g] : 0.f;
#pragma unroll
    for (int nt = 0; nt < 8; nt++) {
        int coff = nt * 8 + t4 * 2;
        if (r0g < N)
            *(__half2*)(H + (size_t)r0g * C + coff) =
                __floats2half2_rn(d[nt][0] * dn0, d[nt][1] * dn0);
        if (r1g < N)
            *(__half2*)(H + (size_t)r1g * C + coff) =
                __floats2half2_rn(d[nt][2] * dn1, d[nt][3] * dn1);
    }
}

__global__ void __launch_bounds__(256) k_gemm_h(const __half* __restrict__ X,
                                                const __half* __restrict__ Wh,
                                                __half* __restrict__ H, int N) {
    gemm_body<__half>(X, Wh, H, N, blockIdx.x);
}

__global__ void __launch_bounds__(256) k_gemm_scatter(
        const float* __restrict__ X, const __half* __restrict__ Wh,
        __half* __restrict__ H, int N,
        const void* __restrict__ eiv, int E, int SB) {
    if (blockIdx.x < SB) scatter_body(eiv, E, blockIdx.x);
    else                 gemm_body<float>(X, Wh, H, N, blockIdx.x - SB);
}

// ---------------- aggregation: 16-edge outer iterations, dual stream ---------
// 4 nodes per warp (8-lane groups). Two interleaved 8-edge streams (A: edges
// j, B: edges j+8) with independent fp16 accumulator banks -> 2x gather MLP.
// fp32 epilogue (self term, dinv, bias).
template <bool HALF_OUT, bool RELU>
__global__ void __launch_bounds__(256) k_agg(const __half* __restrict__ H,
                                             const float* __restrict__ bias,
                                             void* __restrict__ outv, int N) {
    const unsigned F = 0xffffffffu;
    int gid  = blockIdx.x * blockDim.x + threadIdx.x;
    int warp = gid >> 5;
    int lane = gid & 31;
    int g    = lane >> 3;
    int l8   = lane & 7;
    int gb   = g << 3;          // group lane base
    int n    = warp * 4 + g;
    bool act = (n < N);

    int beg = 0, len = 0;
    if (act) { beg = g_rowptr[n]; len = g_deg[n]; }
    int lm = len;
    lm = max(lm, __shfl_xor_sync(F, lm, 8));
    lm = max(lm, __shfl_xor_sync(F, lm, 16));

    const uint32_t ONE2 = 0x3C003C00u;   // half2(1,1)
    __half2 A0[4], A1[4];
#pragma unroll
    for (int i = 0; i < 4; i++) {
        A0[i] = __floats2half2_rn(0.f, 0.f);
        A1[i] = __floats2half2_rn(0.f, 0.f);
    }

    for (int off = 0; off < lm; off += 16) {
        int cnt = min(len - off, 16);                 // may be <= 0
        int spA = (l8     < cnt) ? g_col[beg + off + l8]     : 0;
        int spB = (l8 + 8 < cnt) ? g_col[beg + off + 8 + l8] : 0;
        int cm  = cnt;
        cm = max(cm, __shfl_xor_sync(F, cm, 8));
        cm = max(cm, __shfl_xor_sync(F, cm, 16));

        if (cm > 8) {
            // combined: 8 iterations, 2 edges each (A: j, B: j+8)
#pragma unroll
            for (int j = 0; j < 8; j++) {
                int sA = __shfl_sync(F, spA, gb + j);
                int sB = __shfl_sync(F, spB, gb + j);
                uint32_t mAb = (j     < cnt) ? ONE2 : 0u;
                uint32_t mBb = (j + 8 < cnt) ? ONE2 : 0u;
                __half2 mA = *(__half2*)&mAb;
                __half2 mB = *(__half2*)&mBb;
                uint4 vA = *(const uint4*)(H + (size_t)sA * C + l8 * 8);
                uint4 vB = *(const uint4*)(H + (size_t)sB * C + l8 * 8);
                __half2* a = (__half2*)&vA;
                __half2* b = (__half2*)&vB;
                A0[0] = __hfma2(a[0], mA, A0[0]);
                A1[0] = __hfma2(b[0], mB, A1[0]);
                A0[1] = __hfma2(a[1], mA, A0[1]);
                A1[1] = __hfma2(b[1], mB, A1[1]);
                A0[2] = __hfma2(a[2], mA, A0[2]);
                A1[2] = __hfma2(b[2], mB, A1[2]);
                A0[3] = __hfma2(a[3], mA, A0[3]);
                A1[3] = __hfma2(b[3], mB, A1[3]);
            }
        } else {
            // A-only tail: cm <= 8 across the warp
#pragma unroll 4
            for (int j = 0; j < cm; j++) {
                int sA = __shfl_sync(F, spA, gb + j);
                uint32_t mAb = (j < cnt) ? ONE2 : 0u;
                __half2 mA = *(__half2*)&mAb;
                uint4 vA = *(const uint4*)(H + (size_t)sA * C + l8 * 8);
                __half2* a = (__half2*)&vA;
                A0[0] = __hfma2(a[0], mA, A0[0]);
                A0[1] = __hfma2(a[1], mA, A0[1]);
                A0[2] = __hfma2(a[2], mA, A0[2]);
                A0[3] = __hfma2(a[3], mA, A0[3]);
            }
        }
    }

    if (act) {
        float2 e0 = __half22float2(A0[0]), o0 = __half22float2(A1[0]);
        float2 e1 = __half22float2(A0[1]), o1 = __half22float2(A1[1]);
        float2 e2 = __half22float2(A0[2]), o2 = __half22float2(A1[2]);
        float2 e3 = __half22float2(A0[3]), o3 = __half22float2(A1[3]);
        float a0 = e0.x + o0.x, a1 = e0.y + o0.y;
        float a2 = e1.x + o1.x, a3 = e1.y + o1.y;
        float a4 = e2.x + o2.x, a5 = e2.y + o2.y;
        float a6 = e3.x + o3.x, a7 = e3.y + o3.y;

        float dn = g_dinv[n];
        uint4 hv = *(const uint4*)(H + (size_t)n * C + l8 * 8);
        float2 h0 = __half22float2(*(__half2*)&hv.x);
        float2 h1 = __half22float2(*(__half2*)&hv.y);
        float2 h2 = __half22float2(*(__half2*)&hv.z);
        float2 h3 = __half22float2(*(__half2*)&hv.w);
        float4 bA = *(const float4*)(bias + l8 * 8);
        float4 bB = *(const float4*)(bias + l8 * 8 + 4);
        float r0 = dn * (a0 + h0.x) + bA.x;
        float r1 = dn * (a1 + h0.y) + bA.y;
        float r2 = dn * (a2 + h1.x) + bA.z;
        float r3 = dn * (a3 + h1.y) + bA.w;
        float r4 = dn * (a4 + h2.x) + bB.x;
        float r5 = dn * (a5 + h2.y) + bB.y;
        float r6 = dn * (a6 + h3.x) + bB.z;
        float r7 = dn * (a7 + h3.y) + bB.w;
        if (RELU) {
            r0 = fmaxf(r0, 0.f); r1 = fmaxf(r1, 0.f);
            r2 = fmaxf(r2, 0.f); r3 = fmaxf(r3, 0.f);
            r4 = fmaxf(r4, 0.f); r5 = fmaxf(r5, 0.f);
            r6 = fmaxf(r6, 0.f); r7 = fmaxf(r7, 0.f);
        }
        if (HALF_OUT) {
            __half2 q0 = __floats2half2_rn(r0, r1);
            __half2 q1 = __floats2half2_rn(r2, r3);
            __half2 q2 = __floats2half2_rn(r4, r5);
            __half2 q3 = __floats2half2_rn(r6, r7);
            uint4 pk = make_uint4(*(uint32_t*)&q0, *(uint32_t*)&q1,
                                  *(uint32_t*)&q2, *(uint32_t*)&q3);
            *(uint4*)((__half*)outv + (size_t)n * C + l8 * 8) = pk;
        } else {
            float* o = (float*)outv + (size_t)n * C + l8 * 8;
            *(float4*)o       = make_float4(r0, r1, r2, r3);
            *(float4*)(o + 4) = make_float4(r4, r5, r6, r7);
        }
    }
}

// ---------------- launch ------------------------------------------------------
extern "C" void kernel_launch(void* const* d_in, const int* in_sizes, int n_in,
                              void* d_out, int out_size) {
    const float* x   = (const float*)d_in[0];
    const void*  ei  = d_in[1];
    const float* W1  = (const float*)d_in[2];
    const float* b1  = (const float*)d_in[3];
    const float* W2  = (const float*)d_in[4];
    const float* b2  = (const float*)d_in[5];
    float*       out = (float*)d_out;

    int N = in_sizes[0] / C;     // 100000
    int E = in_sizes[1] / 2;     // 1200000

    __half* ha;  cudaGetSymbolAddress((void**)&ha, g_ha);
    __half* hb;  cudaGetSymbolAddress((void**)&hb, g_hb);
    __half* w1h; cudaGetSymbolAddress((void**)&w1h, g_w1h);
    __half* w2h; cudaGetSymbolAddress((void**)&w2h, g_w2h);

    int CH  = (N + NB_PRE - 1) / NB_PRE;
    int SB  = (E + 255) / 256;
    int GB  = (N + 127) / 128;
    int AGB = (N + 31) / 32;

    k_pre<<<NB_PRE, 256>>>(ei, W1, W2, E, N, CH);
    k_gemm_scatter<<<SB + GB, 256>>>(x, w1h, ha, N, ei, E, SB);
    k_agg<true, true><<<AGB, 256>>>(ha, b1, hb, N);
    k_gemm_h<<<GB, 256>>>(hb, w2h, ha, N);
    k_agg<false, false><<<AGB, 256>>>(ha, b2, out, N);
}